// round 17
// baseline (speedup 1.0000x reference)
#include <cuda_runtime.h>

#define T_FIXED 131072
#define HID 64
#define CHUNK_BODY 256
#define CHUNK_BURN 32

// ---- scratch (static __device__, allocation-free) ----
__device__ float g_xr[(size_t)HID * T_FIXED];   // [k][t] transposed
__device__ float g_xz[(size_t)HID * T_FIXED];
__device__ float g_xn[(size_t)HID * T_FIXED];
__device__ float g_hs[(size_t)HID * T_FIXED];   // [k][t] transposed

// ---- f32x2 helpers (packed fp32 pair ops, sm_103a) ----
__device__ __forceinline__ unsigned long long pack2(float lo, float hi) {
    unsigned long long r;
    asm("mov.b64 %0, {%1, %2};" : "=l"(r) : "f"(lo), "f"(hi));
    return r;
}
__device__ __forceinline__ float2 unpack2(unsigned long long v) {
    float2 r;
    asm("mov.b64 {%0, %1}, %2;" : "=f"(r.x), "=f"(r.y) : "l"(v));
    return r;
}
__device__ __forceinline__ void fma2(unsigned long long& acc, unsigned long long a, unsigned long long b) {
    asm("fma.rn.f32x2 %0, %1, %2, %0;" : "+l"(acc) : "l"(a), "l"(b));
}
// ---- HW tanh (MUFU.TANH; validated fast + accurate enough r16) ----
__device__ __forceinline__ float tanh_hw(float x) {
    float y;
    asm("tanh.approx.f32 %0, %1;" : "=f"(y) : "f"(x));
    return y;
}
__device__ __forceinline__ float sigmoid_hw(float x) {
    return fmaf(0.5f, tanh_hw(0.5f * x), 0.5f);   // sig(x) = (1+tanh(x/2))/2
}

// =====================================================================
// Kernel 1 (r11/r16 version, 109us): hs_in = relu(x @ W1 + b1);
// xr/xz/xn = hs_in @ Wi* + bi*. Outputs transposed [k][T].
// =====================================================================
__global__ void __launch_bounds__(256, 2) k1(
    const float* __restrict__ obs, const float* __restrict__ W1, const float* __restrict__ b1,
    const float* __restrict__ Wir, const float* __restrict__ bir,
    const float* __restrict__ Wiz, const float* __restrict__ biz,
    const float* __restrict__ Win, const float* __restrict__ bin_,
    float* __restrict__ xr, float* __restrict__ xz, float* __restrict__ xn, int T)
{
    extern __shared__ float sm[];              // 20544 floats
    float* sh_hin = sm;                        // [64][256] = 16384 (phase B)
    float* sW     = sm + 16384;                // 4096 (one gate matrix)
    float* sbias  = sm + 20480;                // 64
    const int tid = threadIdx.x;

    // ---------- Phase A ----------
    {
        float* sW1 = sm;                       // 2304
        float* sx  = sm + 2304;                // 256*37 = 9472
        for (int idx = tid; idx < 2304; idx += 256) sW1[idx] = W1[idx];
        size_t base = (size_t)blockIdx.x * (256 * 36);
        for (int idx = tid; idx < 256 * 36; idx += 256) {
            int tl = idx / 36, i = idx - tl * 36;
            sx[tl * 37 + i] = obs[base + idx];
        }
        __syncthreads();

        float hin[64];
#pragma unroll
        for (int j = 0; j < 64; ++j) hin[j] = b1[j];
        for (int i = 0; i < 36; ++i) {
            float xi = sx[tid * 37 + i];
            const float4* w4 = (const float4*)(sW1 + i * 64);
#pragma unroll
            for (int j4 = 0; j4 < 16; ++j4) {
                float4 w = w4[j4];
                hin[4 * j4 + 0] = fmaf(xi, w.x, hin[4 * j4 + 0]);
                hin[4 * j4 + 1] = fmaf(xi, w.y, hin[4 * j4 + 1]);
                hin[4 * j4 + 2] = fmaf(xi, w.z, hin[4 * j4 + 2]);
                hin[4 * j4 + 3] = fmaf(xi, w.w, hin[4 * j4 + 3]);
            }
        }
        __syncthreads();
#pragma unroll
        for (int j = 0; j < 64; ++j)
            sh_hin[j * 256 + tid] = fmaxf(hin[j], 0.f);
    }

    // ---------- Phase B: 3 gate passes ----------
    const int tg = tid & 63;
    const int kt = tid >> 6;
    const int k0 = kt * 16;
    const int tl = tg * 4;
    const size_t tglob = (size_t)blockIdx.x * 256 + tl;

#pragma unroll 1
    for (int g = 0; g < 3; ++g) {
        const float* Wg = (g == 0) ? Wir : (g == 1) ? Wiz : Win;
        const float* bg = (g == 0) ? bir : (g == 1) ? biz : bin_;
        float* xg       = (g == 0) ? xr  : (g == 1) ? xz  : xn;

        __syncthreads();
        for (int idx = tid; idx < 4096; idx += 256) sW[idx] = Wg[idx];
        if (tid < 64) sbias[tid] = bg[tid];
        __syncthreads();

        unsigned long long acc[8][4];
#pragma unroll
        for (int p = 0; p < 8; ++p) {
            float2 b2 = *(const float2*)(sbias + k0 + 2 * p);
            unsigned long long bp = pack2(b2.x, b2.y);
#pragma unroll
            for (int ti = 0; ti < 4; ++ti) acc[p][ti] = bp;
        }

#pragma unroll 4
        for (int j = 0; j < 64; ++j) {
            float4 h4 = *(const float4*)(sh_hin + j * 256 + tl);
            unsigned long long hd0 = pack2(h4.x, h4.x);
            unsigned long long hd1 = pack2(h4.y, h4.y);
            unsigned long long hd2 = pack2(h4.z, h4.z);
            unsigned long long hd3 = pack2(h4.w, h4.w);
            const ulonglong2* w2 = (const ulonglong2*)(sW + j * 64 + k0);
            ulonglong2 wa = w2[0], wb = w2[1], wc = w2[2], wd = w2[3];
            fma2(acc[0][0], hd0, wa.x); fma2(acc[0][1], hd1, wa.x);
            fma2(acc[0][2], hd2, wa.x); fma2(acc[0][3], hd3, wa.x);
            fma2(acc[1][0], hd0, wa.y); fma2(acc[1][1], hd1, wa.y);
            fma2(acc[1][2], hd2, wa.y); fma2(acc[1][3], hd3, wa.y);
            fma2(acc[2][0], hd0, wb.x); fma2(acc[2][1], hd1, wb.x);
            fma2(acc[2][2], hd2, wb.x); fma2(acc[2][3], hd3, wb.x);
            fma2(acc[3][0], hd0, wb.y); fma2(acc[3][1], hd1, wb.y);
            fma2(acc[3][2], hd2, wb.y); fma2(acc[3][3], hd3, wb.y);
            fma2(acc[4][0], hd0, wc.x); fma2(acc[4][1], hd1, wc.x);
            fma2(acc[4][2], hd2, wc.x); fma2(acc[4][3], hd3, wc.x);
            fma2(acc[5][0], hd0, wc.y); fma2(acc[5][1], hd1, wc.y);
            fma2(acc[5][2], hd2, wc.y); fma2(acc[5][3], hd3, wc.y);
            fma2(acc[6][0], hd0, wd.x); fma2(acc[6][1], hd1, wd.x);
            fma2(acc[6][2], hd2, wd.x); fma2(acc[6][3], hd3, wd.x);
            fma2(acc[7][0], hd0, wd.y); fma2(acc[7][1], hd1, wd.y);
            fma2(acc[7][2], hd2, wd.y); fma2(acc[7][3], hd3, wd.y);
        }

#pragma unroll
        for (int p = 0; p < 8; ++p) {
            int k = k0 + 2 * p;
            float2 u0 = unpack2(acc[p][0]);
            float2 u1 = unpack2(acc[p][1]);
            float2 u2 = unpack2(acc[p][2]);
            float2 u3 = unpack2(acc[p][3]);
            float4 lo = make_float4(u0.x, u1.x, u2.x, u3.x);
            float4 hi = make_float4(u0.y, u1.y, u2.y, u3.y);
            *(float4*)(xg + (size_t)k * T + tglob)       = lo;
            *(float4*)(xg + (size_t)(k + 1) * T + tglob) = hi;
        }
    }
}

// =====================================================================
// Kernel 2: TWO-CHUNK INTERLEAVED recurrence. grid = T/512 CTAs of
// 128 threads. CTA b owns chunks A=2b, B=2b+1 (body 256, burn 32 each);
// the same weight registers serve both; per superstep A/B chains
// interleave to hide latency and ONE barrier covers both h exchanges.
// =====================================================================
__device__ __forceinline__ void step2(
    const float* __restrict__ hArd, float* __restrict__ hAwr,
    const float* __restrict__ hBrd, float* __restrict__ hBwr,
    const unsigned long long* wr, const unsigned long long* wz, const unsigned long long* wn,
    float bn, float xrA, float xzA, float xnA, float xrB, float xzB, float xnB,
    float& hA, float& hB, int k, int half)
{
    unsigned long long aAr = 0, aAz = 0, aAn = 0, aBr = 0, aBz = 0, aBn = 0;
    const int off = half * 32;
#pragma unroll
    for (int ph = 0; ph < 2; ++ph) {
        unsigned long long hpA[8], hpB[8];
        const ulonglong2* a2 = (const ulonglong2*)(hArd + off + ph * 16);
        const ulonglong2* b2 = (const ulonglong2*)(hBrd + off + ph * 16);
#pragma unroll
        for (int q = 0; q < 4; ++q) {
            ulonglong2 va = a2[q]; hpA[2 * q] = va.x; hpA[2 * q + 1] = va.y;
            ulonglong2 vb = b2[q]; hpB[2 * q] = vb.x; hpB[2 * q + 1] = vb.y;
        }
#pragma unroll
        for (int i = 0; i < 8; ++i) {
            fma2(aAr, hpA[i], wr[ph * 8 + i]);
            fma2(aBr, hpB[i], wr[ph * 8 + i]);
            fma2(aAz, hpA[i], wz[ph * 8 + i]);
            fma2(aBz, hpB[i], wz[ph * 8 + i]);
            fma2(aAn, hpA[i], wn[ph * 8 + i]);
            fma2(aBn, hpB[i], wn[ph * 8 + i]);
        }
    }
    float2 f;
    f = unpack2(aAr); float drA = f.x + f.y;
    f = unpack2(aBr); float drB = f.x + f.y;
    f = unpack2(aAn); float dnA = f.x + f.y;
    f = unpack2(aBn); float dnB = f.x + f.y;
    f = unpack2(aAz); float dzA = f.x + f.y;
    f = unpack2(aBz); float dzB = f.x + f.y;
    drA += __shfl_xor_sync(0xffffffffu, drA, 1);
    drB += __shfl_xor_sync(0xffffffffu, drB, 1);
    float rA = sigmoid_hw(xrA + drA);
    float rB = sigmoid_hw(xrB + drB);
    dnA += __shfl_xor_sync(0xffffffffu, dnA, 1);
    dnB += __shfl_xor_sync(0xffffffffu, dnB, 1);
    dzA += __shfl_xor_sync(0xffffffffu, dzA, 1);
    dzB += __shfl_xor_sync(0xffffffffu, dzB, 1);
    float zA = sigmoid_hw(xzA + dzA);
    float zB = sigmoid_hw(xzB + dzB);
    float nA = tanh_hw(fmaf(rA, dnA + bn, xnA));
    float nB = tanh_hw(fmaf(rB, dnB + bn, xnB));
    hA = fmaf(zA, hA - nA, nA);
    hB = fmaf(zB, hB - nB, nB);
    if (!half) { hAwr[k] = hA; hBwr[k] = hB; }
}

__global__ void __launch_bounds__(128) k2(
    const float* __restrict__ xr, const float* __restrict__ xz, const float* __restrict__ xn,
    const float* __restrict__ Whr, const float* __restrict__ Whz, const float* __restrict__ Whn,
    const float* __restrict__ bhn, float* __restrict__ hsT, int T)
{
    __shared__ __align__(16) float hsmA[2][64];
    __shared__ __align__(16) float hsmB[2][64];
    const int tid = threadIdx.x;
    const int k = tid >> 1, half = tid & 1;
    const int base = half * 32;

    unsigned long long wr[16], wz[16], wn[16];
#pragma unroll
    for (int i = 0; i < 16; ++i) {
        int row = base + 2 * i;
        wr[i] = pack2(Whr[row * 64 + k], Whr[(row + 1) * 64 + k]);
        wz[i] = pack2(Whz[row * 64 + k], Whz[(row + 1) * 64 + k]);
        wn[i] = pack2(Whn[row * 64 + k], Whn[(row + 1) * 64 + k]);
    }
    const float bn = bhn[k];
    if (tid < 64) {
        hsmA[0][tid] = 0.f; hsmA[1][tid] = 0.f;
        hsmB[0][tid] = 0.f; hsmB[1][tid] = 0.f;
    }

    const int tA_body = blockIdx.x * (2 * CHUNK_BODY);
    const int tB_body = tA_body + CHUNK_BODY;
    const int tA_burn = (blockIdx.x == 0) ? 0 : tA_body - CHUNK_BURN;
    const int tB_burn = tB_body - CHUNK_BURN;

    const float* pr = xr + (size_t)k * T;
    const float* pz = xz + (size_t)k * T;
    const float* pn = xn + (size_t)k * T;
    float* pout = hsT + (size_t)k * T;

    float4 frA = *(const float4*)(pr + tA_burn);
    float4 fzA = *(const float4*)(pz + tA_burn);
    float4 fnA = *(const float4*)(pn + tA_burn);
    float4 frB = *(const float4*)(pr + tB_burn);
    float4 fzB = *(const float4*)(pz + tB_burn);
    float4 fnB = *(const float4*)(pn + tB_burn);
    float hA = 0.f, hB = 0.f;
    __syncthreads();

    // -------- burn-in: 32 steps each chunk, interleaved --------
    for (int i = 0; i < CHUNK_BURN; i += 4) {
        float4 nrA = *(const float4*)(pr + tA_burn + i + 4);
        float4 nzA = *(const float4*)(pz + tA_burn + i + 4);
        float4 nnA = *(const float4*)(pn + tA_burn + i + 4);
        float4 nrB = *(const float4*)(pr + tB_burn + i + 4);
        float4 nzB = *(const float4*)(pz + tB_burn + i + 4);
        float4 nnB = *(const float4*)(pn + tB_burn + i + 4);

        step2(hsmA[0], hsmA[1], hsmB[0], hsmB[1], wr, wz, wn, bn,
              frA.x, fzA.x, fnA.x, frB.x, fzB.x, fnB.x, hA, hB, k, half);
        __syncthreads();
        step2(hsmA[1], hsmA[0], hsmB[1], hsmB[0], wr, wz, wn, bn,
              frA.y, fzA.y, fnA.y, frB.y, fzB.y, fnB.y, hA, hB, k, half);
        __syncthreads();
        step2(hsmA[0], hsmA[1], hsmB[0], hsmB[1], wr, wz, wn, bn,
              frA.z, fzA.z, fnA.z, frB.z, fzB.z, fnB.z, hA, hB, k, half);
        __syncthreads();
        step2(hsmA[1], hsmA[0], hsmB[1], hsmB[0], wr, wz, wn, bn,
              frA.w, fzA.w, fnA.w, frB.w, fzB.w, fnB.w, hA, hB, k, half);
        __syncthreads();

        frA = nrA; fzA = nzA; fnA = nnA;
        frB = nrB; fzB = nzB; fnB = nnB;
    }

    // -------- chunk 0 special-case: body must start from h=0 at t=0 --------
    if (blockIdx.x == 0) {
        hA = 0.f;
        if (!half) hsmA[0][k] = 0.f;
        frA = *(const float4*)(pr);
        fzA = *(const float4*)(pz);
        fnA = *(const float4*)(pn);
    }
    __syncthreads();

    // -------- body: 256 steps each chunk, stores every 4 --------
    for (int t = 0; t < CHUNK_BODY; t += 4) {
        int tn = (t + 4 < CHUNK_BODY) ? t + 4 : t;
        float4 nrA = *(const float4*)(pr + tA_body + tn);
        float4 nzA = *(const float4*)(pz + tA_body + tn);
        float4 nnA = *(const float4*)(pn + tA_body + tn);
        float4 nrB = *(const float4*)(pr + tB_body + tn);
        float4 nzB = *(const float4*)(pz + tB_body + tn);
        float4 nnB = *(const float4*)(pn + tB_body + tn);

        float oA0, oA1, oA2, oA3, oB0, oB1, oB2, oB3;
        step2(hsmA[0], hsmA[1], hsmB[0], hsmB[1], wr, wz, wn, bn,
              frA.x, fzA.x, fnA.x, frB.x, fzB.x, fnB.x, hA, hB, k, half);
        oA0 = hA; oB0 = hB;
        __syncthreads();
        step2(hsmA[1], hsmA[0], hsmB[1], hsmB[0], wr, wz, wn, bn,
              frA.y, fzA.y, fnA.y, frB.y, fzB.y, fnB.y, hA, hB, k, half);
        oA1 = hA; oB1 = hB;
        __syncthreads();
        step2(hsmA[0], hsmA[1], hsmB[0], hsmB[1], wr, wz, wn, bn,
              frA.z, fzA.z, fnA.z, frB.z, fzB.z, fnB.z, hA, hB, k, half);
        oA2 = hA; oB2 = hB;
        __syncthreads();
        step2(hsmA[1], hsmA[0], hsmB[1], hsmB[0], wr, wz, wn, bn,
              frA.w, fzA.w, fnA.w, frB.w, fzB.w, fnB.w, hA, hB, k, half);
        oA3 = hA; oB3 = hB;
        __syncthreads();

        if (half) {     // odd lane streams h to gmem, off the critical path
            __stcs((float4*)(pout + tA_body + t), make_float4(oA0, oA1, oA2, oA3));
            __stcs((float4*)(pout + tB_body + t), make_float4(oB0, oB1, oB2, oB3));
        }
        frA = nrA; fzA = nzA; fnA = nnA;
        frB = nrB; fzB = nzB; fnB = nnB;
    }
}

// =====================================================================
// Kernel 3 (parallel over T): out[t][p] = hsT[:,t] . Wend[:, p^1] + bend[p^1]
// =====================================================================
__global__ void __launch_bounds__(256) k3(
    const float* __restrict__ hsT, const float* __restrict__ Wend,
    const float* __restrict__ bend, float* __restrict__ out, int T)
{
    __shared__ float sw[256];
    __shared__ float sb[4];
    const int tid = threadIdx.x;
    sw[tid] = Wend[tid];
    if (tid < 4) sb[tid] = bend[tid];
    __syncthreads();

    const int t = blockIdx.x * 256 + tid;
    float a0 = sb[0], a1 = sb[1], a2 = sb[2], a3 = sb[3];
#pragma unroll 8
    for (int k = 0; k < 64; ++k) {
        float h = __ldg(hsT + (size_t)k * T + t);
        a0 = fmaf(h, sw[4 * k + 0], a0);
        a1 = fmaf(h, sw[4 * k + 1], a1);
        a2 = fmaf(h, sw[4 * k + 2], a2);
        a3 = fmaf(h, sw[4 * k + 3], a3);
    }
    float4 o = make_float4(a1, a0, a3, a2);   // PERM [1,0,3,2] == p^1
    *(float4*)(out + (size_t)t * 4) = o;
}

// =====================================================================
extern "C" void kernel_launch(void* const* d_in, const int* in_sizes, int n_in,
                              void* d_out, int out_size)
{
    const float* obs  = (const float*)d_in[0];
    const float* W1   = (const float*)d_in[1];
    const float* b1   = (const float*)d_in[2];
    const float* Wir  = (const float*)d_in[3];
    const float* bir  = (const float*)d_in[4];
    const float* Wiz  = (const float*)d_in[5];
    const float* biz  = (const float*)d_in[6];
    const float* Win  = (const float*)d_in[7];
    const float* bin_ = (const float*)d_in[8];
    const float* Whr  = (const float*)d_in[9];
    const float* Whz  = (const float*)d_in[10];
    const float* Whn  = (const float*)d_in[11];
    const float* bhn  = (const float*)d_in[12];
    const float* Wend = (const float*)d_in[13];
    const float* bend = (const float*)d_in[14];
    float* out = (float*)d_out;
    int T = in_sizes[0] / 36;
    if (T > T_FIXED) T = T_FIXED;

    float *xr, *xz, *xn, *hs;
    cudaGetSymbolAddress((void**)&xr, g_xr);
    cudaGetSymbolAddress((void**)&xz, g_xz);
    cudaGetSymbolAddress((void**)&xn, g_xn);
    cudaGetSymbolAddress((void**)&hs, g_hs);

    const int SMEM1 = 20544 * 4;   // 82.2KB: hin 64KB + W 16KB + bias
    cudaFuncSetAttribute(k1, cudaFuncAttributeMaxDynamicSharedMemorySize, SMEM1);

    k1<<<T / 256, 256, SMEM1>>>(obs, W1, b1, Wir, bir, Wiz, biz, Win, bin_, xr, xz, xn, T);
    k2<<<T / (2 * CHUNK_BODY), 128>>>(xr, xz, xn, Whr, Whz, Whn, bhn, hs, T);
    k3<<<T / 256, 256>>>(hs, Wend, bend, out, T);
}